// round 3
// baseline (speedup 1.0000x reference)
#include <cuda_runtime.h>
#include <cuda_bf16.h>

#define NOUT 7
#define NS 14                      // OUT * RATIO sample points per axis
#define NCH 256
#define NBIN 49
#define NTAP 16                    // 2x2 samples * 4 bilinear taps
#define ELEMS (NCH * NBIN)         // 12544 per ROI

__global__ __launch_bounds__(256) void roi_pooler_kernel(
    const float* __restrict__ f0, const float* __restrict__ f1,
    const float* __restrict__ f2, const float* __restrict__ f3,
    const float* __restrict__ boxes, const int* __restrict__ bidx,
    float* __restrict__ out)
{
    const int roi = blockIdx.x;
    const int tid = threadIdx.x;

    __shared__ const float* sBase;   // feature base ptr incl. batch offset
    __shared__ int sHW;              // H*W (channel stride)
    __shared__ int sH, sW;
    __shared__ float sX0, sY0, sBw, sBh;
    __shared__ int   sYloW[NS], sYhiW[NS], sXlo[NS], sXhi[NS];
    __shared__ float sWyl[NS], sWyh[NS], sWxl[NS], sWxh[NS];
    __shared__ int   sOff[NBIN * NTAP];   // per-bin tap offsets (within channel)
    __shared__ float sWt [NBIN * NTAP];   // per-bin tap weights (incl. 0.25 mean)

    if (tid == 0) {
        const float x0 = boxes[roi * 4 + 0];
        const float y0 = boxes[roi * 4 + 1];
        const float x1 = boxes[roi * 4 + 2];
        const float y1 = boxes[roi * 4 + 3];
        const float area = (x1 - x0) * (y1 - y0);
        const float size = sqrtf(area);
        // lvl = clip(floor(4 + log2(size/224 + 1e-8)), 2, 5) - 2
        float lf = floorf(4.0f + log2f(size / 224.0f + 1e-8f));
        lf = fminf(fmaxf(lf, 2.0f), 5.0f);
        const int lvl = (int)lf - 2;

        const float* fp; int H, W; float sc;
        switch (lvl) {
            case 0:  fp = f0; H = 200; W = 304; sc = 0.25f;    break;
            case 1:  fp = f1; H = 100; W = 152; sc = 0.125f;   break;
            case 2:  fp = f2; H =  50; W =  76; sc = 0.0625f;  break;
            default: fp = f3; H =  25; W =  38; sc = 0.03125f; break;
        }
        const int b = bidx[roi];
        sBase = fp + (size_t)b * NCH * H * W;
        sH = H; sW = W; sHW = H * W;
        sX0 = x0 * sc - 0.5f;
        sY0 = y0 * sc - 0.5f;
        sBw = (x1 - x0) * sc * (1.0f / NOUT);
        sBh = (y1 - y0) * sc * (1.0f / NOUT);
    }
    __syncthreads();

    // Axis weights: threads [0,14) handle x, [14,28) handle y.
    if (tid < 2 * NS) {
        const int  s   = (tid < NS) ? tid : tid - NS;
        const bool isY = (tid >= NS);
        const float off = (s + 0.5f) * 0.5f;   // s//2 + (s%2 + 0.5)/2
        const float c   = isY ? (sY0 + sBh * off) : (sX0 + sBw * off);
        const int   n   = isY ? sH : sW;
        const float fn  = (float)n;
        const float valid = (c >= -1.0f && c <= fn) ? 1.0f : 0.0f;
        const float cc    = fmaxf(c, 0.0f);
        const float lo_f  = floorf(cc);
        const bool  cap   = (lo_f >= fn - 1.0f);
        const int   lo    = cap ? (n - 1) : (int)lo_f;
        const int   hi    = cap ? (n - 1) : (lo + 1);
        const float l     = cap ? 0.0f : (cc - lo_f);
        const float wl    = (1.0f - l) * valid;
        const float wh    = l * valid;
        if (isY) {
            sYloW[s] = lo * sW; sYhiW[s] = hi * sW;
            sWyl[s] = wl;       sWyh[s] = wh;
        } else {
            sXlo[s] = lo;       sXhi[s] = hi;
            sWxl[s] = wl;       sWxh[s] = wh;
        }
    }
    __syncthreads();

    // Build per-bin tap tables: 49 bins x 16 taps.
    // tap index k: sy = k>>3, sx = (k>>2)&1, tap = k&3
    //   tap<2 -> y-lo row, tap&1 -> x-hi col
    for (int t = tid; t < NBIN * NTAP; t += 256) {
        const int bin = t >> 4;
        const int k   = t & 15;
        const int sy  = k >> 3;
        const int sx  = (k >> 2) & 1;
        const int tap = k & 3;
        const int ph  = bin / 7;
        const int pw  = bin - ph * 7;
        const int iy  = ph * 2 + sy;
        const int ix  = pw * 2 + sx;
        const int row = (tap < 2)  ? sYloW[iy] : sYhiW[iy];
        const int col = (tap & 1)  ? sXhi[ix]  : sXlo[ix];
        const float wy = (tap < 2) ? sWyl[iy]  : sWyh[iy];
        const float wx = (tap & 1) ? sWxh[ix]  : sWxl[ix];
        sOff[t] = row + col;
        sWt[t]  = wy * wx * 0.25f;   // fold sample mean
    }
    __syncthreads();

    const float* __restrict__ base = sBase;
    const int HW = sHW;
    float* __restrict__ outRoi = out + (size_t)roi * ELEMS;

    #pragma unroll 1
    for (int e = tid; e < ELEMS; e += 256) {
        const int c   = e / NBIN;
        const int bin = e - c * NBIN;
        const float* __restrict__ fc = base + c * HW;
        const int tb = bin << 4;

        float acc = 0.0f;
        #pragma unroll
        for (int k = 0; k < NTAP; k++) {
            acc += sWt[tb + k] * __ldg(fc + sOff[tb + k]);
        }
        outRoi[e] = acc;
    }
}

extern "C" void kernel_launch(void* const* d_in, const int* in_sizes, int n_in,
                              void* d_out, int out_size) {
    const float* f0    = (const float*)d_in[0];
    const float* f1    = (const float*)d_in[1];
    const float* f2    = (const float*)d_in[2];
    const float* f3    = (const float*)d_in[3];
    const float* boxes = (const float*)d_in[4];
    const int*   bidx  = (const int*)d_in[5];
    float*       out   = (float*)d_out;

    const int M = in_sizes[4] / 4;   // boxes is (M, 4)
    roi_pooler_kernel<<<M, 256>>>(f0, f1, f2, f3, boxes, bidx, out);
}

// round 6
// speedup vs baseline: 2.9344x; 2.9344x over previous
#include <cuda_runtime.h>
#include <cuda_bf16.h>

#define NOUT 7
#define NS 14                      // OUT * RATIO sample points per axis
#define NCH 256
#define NBIN 49
#define ELEMS (NCH * NBIN)         // 12544 per ROI

__global__ __launch_bounds__(256) void roi_pooler_kernel(
    const float* __restrict__ f0, const float* __restrict__ f1,
    const float* __restrict__ f2, const float* __restrict__ f3,
    const float* __restrict__ boxes, const int* __restrict__ bidx,
    float* __restrict__ out)
{
    const int roi = blockIdx.x;
    const int tid = threadIdx.x;

    __shared__ const float* sBase;   // feature base ptr incl. batch offset
    __shared__ int sHW;              // H*W (channel stride)
    __shared__ int sH, sW;
    __shared__ float sX0, sY0, sBw, sBh;
    __shared__ int   sYloW[NS], sYhiW[NS], sXlo[NS], sXhi[NS];
    __shared__ float sWyl[NS], sWyh[NS], sWxl[NS], sWxh[NS];

    if (tid == 0) {
        const float x0 = boxes[roi * 4 + 0];
        const float y0 = boxes[roi * 4 + 1];
        const float x1 = boxes[roi * 4 + 2];
        const float y1 = boxes[roi * 4 + 3];
        const float area = (x1 - x0) * (y1 - y0);
        const float size = sqrtf(area);
        // lvl = clip(floor(4 + log2(size/224 + 1e-8)), 2, 5) - 2
        float lf = floorf(4.0f + log2f(size / 224.0f + 1e-8f));
        lf = fminf(fmaxf(lf, 2.0f), 5.0f);
        const int lvl = (int)lf - 2;

        const float* fp; int H, W; float sc;
        switch (lvl) {
            case 0:  fp = f0; H = 200; W = 304; sc = 0.25f;    break;
            case 1:  fp = f1; H = 100; W = 152; sc = 0.125f;   break;
            case 2:  fp = f2; H =  50; W =  76; sc = 0.0625f;  break;
            default: fp = f3; H =  25; W =  38; sc = 0.03125f; break;
        }
        const int b = bidx[roi];
        sBase = fp + (size_t)b * NCH * H * W;
        sH = H; sW = W; sHW = H * W;
        sX0 = x0 * sc - 0.5f;
        sY0 = y0 * sc - 0.5f;
        sBw = (x1 - x0) * sc * (1.0f / NOUT);
        sBh = (y1 - y0) * sc * (1.0f / NOUT);
    }
    __syncthreads();

    // Axis weights: threads [0,14) handle x, [14,28) handle y.
    if (tid < 2 * NS) {
        const int  s   = (tid < NS) ? tid : tid - NS;
        const bool isY = (tid >= NS);
        const float off = (s + 0.5f) * 0.5f;   // s//2 + (s%2 + 0.5)/2
        const float c   = isY ? (sY0 + sBh * off) : (sX0 + sBw * off);
        const int   n   = isY ? sH : sW;
        const float fn  = (float)n;
        const float valid = (c >= -1.0f && c <= fn) ? 1.0f : 0.0f;
        const float cc    = fmaxf(c, 0.0f);
        const float lo_f  = floorf(cc);
        const bool  cap   = (lo_f >= fn - 1.0f);
        const int   lo    = cap ? (n - 1) : (int)lo_f;
        const int   hi    = cap ? (n - 1) : (lo + 1);
        const float l     = cap ? 0.0f : (cc - lo_f);
        const float wl    = (1.0f - l) * valid;
        const float wh    = l * valid;
        if (isY) {
            sYloW[s] = lo * sW; sYhiW[s] = hi * sW;
            sWyl[s] = wl;       sWyh[s] = wh;
        } else {
            sXlo[s] = lo;       sXhi[s] = hi;
            sWxl[s] = wl;       sWxh[s] = wh;
        }
    }
    __syncthreads();

    // Thread mapping: slot = tid & 63 -> bin (49 valid), group = tid >> 6 ->
    // starting channel; each thread keeps its bin FIXED, tap metadata lives in
    // registers, and it loops over 64 channels (c = group, group+4, ...).
    const int group = tid >> 6;        // 0..3
    const int bin   = tid & 63;        // 0..63, valid if < 49
    const int binC  = (bin < NBIN) ? bin : 0;   // clamp for safe shared reads
    const int ph    = binC / 7;
    const int pw    = binC - ph * 7;

    // Separable 4x4 tap structure: out = sum_a wy[a] * sum_b wx[b] * f[row_a + col_b]
    int   rowOff[4], colOff[4];
    float wy[4], wx[4];
    {
        const int iy0 = ph * 2, iy1 = iy0 + 1;
        rowOff[0] = sYloW[iy0]; wy[0] = sWyl[iy0] * 0.25f;
        rowOff[1] = sYhiW[iy0]; wy[1] = sWyh[iy0] * 0.25f;
        rowOff[2] = sYloW[iy1]; wy[2] = sWyl[iy1] * 0.25f;
        rowOff[3] = sYhiW[iy1]; wy[3] = sWyh[iy1] * 0.25f;
        const int ix0 = pw * 2, ix1 = ix0 + 1;
        colOff[0] = sXlo[ix0];  wx[0] = sWxl[ix0];
        colOff[1] = sXhi[ix0];  wx[1] = sWxh[ix0];
        colOff[2] = sXlo[ix1];  wx[2] = sWxl[ix1];
        colOff[3] = sXhi[ix1];  wx[3] = sWxh[ix1];
    }

    if (bin < NBIN) {
        const float* __restrict__ base = sBase;
        const int HW = sHW;
        float* __restrict__ outRoi = out + (size_t)roi * ELEMS;

        for (int c = group; c < NCH; c += 4) {
            const float* __restrict__ fc = base + c * HW;
            float acc = 0.0f;
            #pragma unroll
            for (int a = 0; a < 4; a++) {
                const float* __restrict__ fr = fc + rowOff[a];
                float t = 0.0f;
                #pragma unroll
                for (int b = 0; b < 4; b++) {
                    t += wx[b] * __ldg(fr + colOff[b]);
                }
                acc += wy[a] * t;
            }
            outRoi[c * NBIN + bin] = acc;
        }
    }
}

extern "C" void kernel_launch(void* const* d_in, const int* in_sizes, int n_in,
                              void* d_out, int out_size) {
    const float* f0    = (const float*)d_in[0];
    const float* f1    = (const float*)d_in[1];
    const float* f2    = (const float*)d_in[2];
    const float* f3    = (const float*)d_in[3];
    const float* boxes = (const float*)d_in[4];
    const int*   bidx  = (const int*)d_in[5];
    float*       out   = (float*)d_out;

    const int M = in_sizes[4] / 4;   // boxes is (M, 4)
    roi_pooler_kernel<<<M, 256>>>(f0, f1, f2, f3, boxes, bidx, out);
}

// round 7
// speedup vs baseline: 4.0988x; 1.3968x over previous
#include <cuda_runtime.h>
#include <cuda_bf16.h>

#define NOUT 7
#define NS 14                      // OUT * RATIO sample points per axis
#define NCH 256
#define NBIN 49
#define ELEMS (NCH * NBIN)         // 12544 per ROI
#define CH_SPLIT 2                 // grid.y; channels per block = NCH / CH_SPLIT

__global__ __launch_bounds__(256) void roi_pooler_kernel(
    const float* __restrict__ f0, const float* __restrict__ f1,
    const float* __restrict__ f2, const float* __restrict__ f3,
    const float* __restrict__ boxes, const int* __restrict__ bidx,
    float* __restrict__ out)
{
    const int roi = blockIdx.x;
    const int tid = threadIdx.x;

    __shared__ const float* sBase;   // feature base ptr incl. batch offset
    __shared__ int sHW;              // H*W (channel stride)
    __shared__ int sH, sW;
    __shared__ float sX0, sY0, sBw, sBh;
    __shared__ int   sYloW[NS], sYhiW[NS], sXlo[NS], sXhi[NS];
    __shared__ float sWyl[NS], sWyh[NS], sWxl[NS], sWxh[NS];

    if (tid == 0) {
        const float x0 = boxes[roi * 4 + 0];
        const float y0 = boxes[roi * 4 + 1];
        const float x1 = boxes[roi * 4 + 2];
        const float y1 = boxes[roi * 4 + 3];
        const float area = (x1 - x0) * (y1 - y0);
        const float size = sqrtf(area);
        // lvl = clip(floor(4 + log2(size/224 + 1e-8)), 2, 5) - 2
        float lf = floorf(4.0f + log2f(size / 224.0f + 1e-8f));
        lf = fminf(fmaxf(lf, 2.0f), 5.0f);
        const int lvl = (int)lf - 2;

        const float* fp; int H, W; float sc;
        switch (lvl) {
            case 0:  fp = f0; H = 200; W = 304; sc = 0.25f;    break;
            case 1:  fp = f1; H = 100; W = 152; sc = 0.125f;   break;
            case 2:  fp = f2; H =  50; W =  76; sc = 0.0625f;  break;
            default: fp = f3; H =  25; W =  38; sc = 0.03125f; break;
        }
        const int b = bidx[roi];
        sBase = fp + (size_t)b * NCH * H * W;
        sH = H; sW = W; sHW = H * W;
        sX0 = x0 * sc - 0.5f;
        sY0 = y0 * sc - 0.5f;
        sBw = (x1 - x0) * sc * (1.0f / NOUT);
        sBh = (y1 - y0) * sc * (1.0f / NOUT);
    }
    __syncthreads();

    // Axis weights: threads [0,14) handle x, [14,28) handle y.
    if (tid < 2 * NS) {
        const int  s   = (tid < NS) ? tid : tid - NS;
        const bool isY = (tid >= NS);
        const float off = (s + 0.5f) * 0.5f;   // s//2 + (s%2 + 0.5)/2
        const float c   = isY ? (sY0 + sBh * off) : (sX0 + sBw * off);
        const int   n   = isY ? sH : sW;
        const float fn  = (float)n;
        const float valid = (c >= -1.0f && c <= fn) ? 1.0f : 0.0f;
        const float cc    = fmaxf(c, 0.0f);
        const float lo_f  = floorf(cc);
        const bool  cap   = (lo_f >= fn - 1.0f);
        const int   lo    = cap ? (n - 1) : (int)lo_f;
        const int   hi    = cap ? (n - 1) : (lo + 1);
        const float l     = cap ? 0.0f : (cc - lo_f);
        const float wl    = (1.0f - l) * valid;
        const float wh    = l * valid;
        if (isY) {
            sYloW[s] = lo * sW; sYhiW[s] = hi * sW;
            sWyl[s] = wl;       sWyh[s] = wh;
        } else {
            sXlo[s] = lo;       sXhi[s] = hi;
            sWxl[s] = wl;       sWxh[s] = wh;
        }
    }
    __syncthreads();

    // Thread mapping: slot = tid & 63 -> bin (49 valid), group = tid >> 6 ->
    // channel lane; each thread keeps its bin FIXED, tap metadata lives in
    // registers, and it loops over its share of this block's channel slice.
    const int group = tid >> 6;        // 0..3
    const int bin   = tid & 63;        // 0..63, valid if < 49
    const int binC  = (bin < NBIN) ? bin : 0;   // clamp for safe shared reads
    const int ph    = binC / 7;
    const int pw    = binC - ph * 7;

    // Flattened 16-tap form: out = sum_k w[k] * f[off[k]]
    int   off[16];
    float w[16];
    {
        const int iy0 = ph * 2, iy1 = iy0 + 1;
        const int ix0 = pw * 2, ix1 = ix0 + 1;
        int   rowOff[4] = { sYloW[iy0], sYhiW[iy0], sYloW[iy1], sYhiW[iy1] };
        float wy[4]     = { sWyl[iy0] * 0.25f, sWyh[iy0] * 0.25f,
                            sWyl[iy1] * 0.25f, sWyh[iy1] * 0.25f };
        int   colOff[4] = { sXlo[ix0], sXhi[ix0], sXlo[ix1], sXhi[ix1] };
        float wx[4]     = { sWxl[ix0], sWxh[ix0], sWxl[ix1], sWxh[ix1] };
        #pragma unroll
        for (int a = 0; a < 4; a++)
            #pragma unroll
            for (int b = 0; b < 4; b++) {
                off[a * 4 + b] = rowOff[a] + colOff[b];
                w  [a * 4 + b] = wy[a] * wx[b];
            }
    }

    if (bin < NBIN) {
        const float* __restrict__ base = sBase;
        const int HW = sHW;
        const int cb = blockIdx.y * (NCH / CH_SPLIT);   // this block's channel base
        float* __restrict__ outRoi = out + (size_t)roi * ELEMS;

        #pragma unroll 2
        for (int c = group; c < NCH / CH_SPLIT; c += 4) {
            const float* __restrict__ fc = base + (cb + c) * HW;
            float a0 = 0.0f, a1 = 0.0f, a2 = 0.0f, a3 = 0.0f;
            #pragma unroll
            for (int k = 0; k < 16; k += 4) {
                a0 += w[k + 0] * __ldg(fc + off[k + 0]);
                a1 += w[k + 1] * __ldg(fc + off[k + 1]);
                a2 += w[k + 2] * __ldg(fc + off[k + 2]);
                a3 += w[k + 3] * __ldg(fc + off[k + 3]);
            }
            outRoi[(cb + c) * NBIN + bin] = (a0 + a1) + (a2 + a3);
        }
    }
}

extern "C" void kernel_launch(void* const* d_in, const int* in_sizes, int n_in,
                              void* d_out, int out_size) {
    const float* f0    = (const float*)d_in[0];
    const float* f1    = (const float*)d_in[1];
    const float* f2    = (const float*)d_in[2];
    const float* f3    = (const float*)d_in[3];
    const float* boxes = (const float*)d_in[4];
    const int*   bidx  = (const int*)d_in[5];
    float*       out   = (float*)d_out;

    const int M = in_sizes[4] / 4;   // boxes is (M, 4)
    dim3 grid(M, CH_SPLIT);
    roi_pooler_kernel<<<grid, 256>>>(f0, f1, f2, f3, boxes, bidx, out);
}

// round 9
// speedup vs baseline: 6.3614x; 1.5520x over previous
#include <cuda_runtime.h>
#include <cuda_bf16.h>

#define NOUT 7
#define NS 14                      // OUT * RATIO sample points per axis
#define NCH 256
#define NBIN 49
#define ELEMS (NCH * NBIN)         // 12544 per ROI
#define CH_SPLIT 4                 // grid.y; channels per block = NCH / CH_SPLIT

__global__ __launch_bounds__(256) void roi_pooler_kernel(
    const float* __restrict__ f0, const float* __restrict__ f1,
    const float* __restrict__ f2, const float* __restrict__ f3,
    const float* __restrict__ boxes, const int* __restrict__ bidx,
    float* __restrict__ out)
{
    const int roi = blockIdx.x;
    const int tid = threadIdx.x;

    __shared__ const float* sBase;   // feature base ptr incl. batch offset
    __shared__ int sHW;              // H*W (channel stride)
    __shared__ int sH, sW;
    __shared__ float sX0, sY0, sBw, sBh;
    __shared__ int   sYloW[NS], sYhiW[NS], sXlo[NS], sXhi[NS];
    __shared__ float sWyl[NS], sWyh[NS], sWxl[NS], sWxh[NS];

    if (tid == 0) {
        const float x0 = boxes[roi * 4 + 0];
        const float y0 = boxes[roi * 4 + 1];
        const float x1 = boxes[roi * 4 + 2];
        const float y1 = boxes[roi * 4 + 3];
        const float area = (x1 - x0) * (y1 - y0);
        const float size = sqrtf(area);
        // lvl = clip(floor(4 + log2(size/224 + 1e-8)), 2, 5) - 2
        float lf = floorf(4.0f + log2f(size / 224.0f + 1e-8f));
        lf = fminf(fmaxf(lf, 2.0f), 5.0f);
        const int lvl = (int)lf - 2;

        const float* fp; int H, W; float sc;
        switch (lvl) {
            case 0:  fp = f0; H = 200; W = 304; sc = 0.25f;    break;
            case 1:  fp = f1; H = 100; W = 152; sc = 0.125f;   break;
            case 2:  fp = f2; H =  50; W =  76; sc = 0.0625f;  break;
            default: fp = f3; H =  25; W =  38; sc = 0.03125f; break;
        }
        const int b = bidx[roi];
        sBase = fp + (size_t)b * NCH * H * W;
        sH = H; sW = W; sHW = H * W;
        sX0 = x0 * sc - 0.5f;
        sY0 = y0 * sc - 0.5f;
        sBw = (x1 - x0) * sc * (1.0f / NOUT);
        sBh = (y1 - y0) * sc * (1.0f / NOUT);
    }
    __syncthreads();

    // Axis weights: threads [0,14) handle x, [14,28) handle y.
    if (tid < 2 * NS) {
        const int  s   = (tid < NS) ? tid : tid - NS;
        const bool isY = (tid >= NS);
        const float off = (s + 0.5f) * 0.5f;   // s//2 + (s%2 + 0.5)/2
        const float c   = isY ? (sY0 + sBh * off) : (sX0 + sBw * off);
        const int   n   = isY ? sH : sW;
        const float fn  = (float)n;
        const float valid = (c >= -1.0f && c <= fn) ? 1.0f : 0.0f;
        const float cc    = fmaxf(c, 0.0f);
        const float lo_f  = floorf(cc);
        const bool  cap   = (lo_f >= fn - 1.0f);
        const int   lo    = cap ? (n - 1) : (int)lo_f;
        const int   hi    = cap ? (n - 1) : (lo + 1);
        const float l     = cap ? 0.0f : (cc - lo_f);
        const float wl    = (1.0f - l) * valid;
        const float wh    = l * valid;
        if (isY) {
            sYloW[s] = lo * sW; sYhiW[s] = hi * sW;
            sWyl[s] = wl;       sWyh[s] = wh;
        } else {
            sXlo[s] = lo;       sXhi[s] = hi;
            sWxl[s] = wl;       sWxh[s] = wh;
        }
    }
    __syncthreads();

    // Thread mapping: slot = tid & 63 -> bin (49 valid), group = tid >> 6 ->
    // channel lane; each thread keeps its bin FIXED, tap metadata lives in
    // registers, and it loops over its share of this block's channel slice.
    const int group = tid >> 6;        // 0..3
    const int bin   = tid & 63;        // 0..63, valid if < 49
    const int binC  = (bin < NBIN) ? bin : 0;   // clamp for safe shared reads
    const int ph    = binC / 7;
    const int pw    = binC - ph * 7;

    // Flattened 16-tap form: out = sum_k w[k] * f[off[k]]
    int   off[16];
    float w[16];
    {
        const int iy0 = ph * 2, iy1 = iy0 + 1;
        const int ix0 = pw * 2, ix1 = ix0 + 1;
        int   rowOff[4] = { sYloW[iy0], sYhiW[iy0], sYloW[iy1], sYhiW[iy1] };
        float wy[4]     = { sWyl[iy0] * 0.25f, sWyh[iy0] * 0.25f,
                            sWyl[iy1] * 0.25f, sWyh[iy1] * 0.25f };
        int   colOff[4] = { sXlo[ix0], sXhi[ix0], sXlo[ix1], sXhi[ix1] };
        float wx[4]     = { sWxl[ix0], sWxh[ix0], sWxl[ix1], sWxh[ix1] };
        #pragma unroll
        for (int a = 0; a < 4; a++)
            #pragma unroll
            for (int b = 0; b < 4; b++) {
                off[a * 4 + b] = rowOff[a] + colOff[b];
                w  [a * 4 + b] = wy[a] * wx[b];
            }
    }

    if (bin < NBIN) {
        const float* __restrict__ base = sBase;
        const int HW = sHW;
        const int cb = blockIdx.y * (NCH / CH_SPLIT);   // this block's channel base
        float* __restrict__ outRoi = out + (size_t)roi * ELEMS;

        for (int c = group; c < NCH / CH_SPLIT; c += 4) {
            const float* __restrict__ fc = base + (cb + c) * HW;
            float a0 = 0.0f, a1 = 0.0f, a2 = 0.0f, a3 = 0.0f;
            #pragma unroll
            for (int k = 0; k < 16; k += 4) {
                a0 += w[k + 0] * __ldg(fc + off[k + 0]);
                a1 += w[k + 1] * __ldg(fc + off[k + 1]);
                a2 += w[k + 2] * __ldg(fc + off[k + 2]);
                a3 += w[k + 3] * __ldg(fc + off[k + 3]);
            }
            outRoi[(cb + c) * NBIN + bin] = (a0 + a1) + (a2 + a3);
        }
    }
}

extern "C" void kernel_launch(void* const* d_in, const int* in_sizes, int n_in,
                              void* d_out, int out_size) {
    const float* f0    = (const float*)d_in[0];
    const float* f1    = (const float*)d_in[1];
    const float* f2    = (const float*)d_in[2];
    const float* f3    = (const float*)d_in[3];
    const float* boxes = (const float*)d_in[4];
    const int*   bidx  = (const int*)d_in[5];
    float*       out   = (float*)d_out;

    const int M = in_sizes[4] / 4;   // boxes is (M, 4)
    dim3 grid(M, CH_SPLIT);
    roi_pooler_kernel<<<grid, 256>>>(f0, f1, f2, f3, boxes, bidx, out);
}

// round 10
// speedup vs baseline: 7.1319x; 1.1211x over previous
#include <cuda_runtime.h>
#include <cuda_bf16.h>

#define NOUT 7
#define NS 14                      // OUT * RATIO sample points per axis
#define NCH 256
#define NBIN 49
#define ELEMS (NCH * NBIN)         // 12544 per ROI
#define CH_SPLIT 4                 // grid.y; channels per block = NCH / CH_SPLIT
#define CPB (NCH / CH_SPLIT)       // 64 channels per block
#define NGRP 5                     // channel groups per block (5*49 = 245 active threads)

__global__ __launch_bounds__(256) void roi_pooler_kernel(
    const float* __restrict__ f0, const float* __restrict__ f1,
    const float* __restrict__ f2, const float* __restrict__ f3,
    const float* __restrict__ boxes, const int* __restrict__ bidx,
    float* __restrict__ out)
{
    const int roi = blockIdx.x;
    const int tid = threadIdx.x;

    __shared__ const float* sBase;   // feature base ptr incl. batch offset
    __shared__ int sHW;              // H*W (channel stride)
    __shared__ int sH, sW;
    __shared__ float sX0, sY0, sBw, sBh;
    __shared__ int   sYloW[NS], sYhiW[NS], sXlo[NS], sXhi[NS];
    __shared__ float sWyl[NS], sWyh[NS], sWxl[NS], sWxh[NS];

    if (tid == 0) {
        const float x0 = boxes[roi * 4 + 0];
        const float y0 = boxes[roi * 4 + 1];
        const float x1 = boxes[roi * 4 + 2];
        const float y1 = boxes[roi * 4 + 3];
        const float area = (x1 - x0) * (y1 - y0);
        const float size = sqrtf(area);
        // lvl = clip(floor(4 + log2(size/224 + 1e-8)), 2, 5) - 2
        float lf = floorf(4.0f + log2f(size / 224.0f + 1e-8f));
        lf = fminf(fmaxf(lf, 2.0f), 5.0f);
        const int lvl = (int)lf - 2;

        const float* fp; int H, W; float sc;
        switch (lvl) {
            case 0:  fp = f0; H = 200; W = 304; sc = 0.25f;    break;
            case 1:  fp = f1; H = 100; W = 152; sc = 0.125f;   break;
            case 2:  fp = f2; H =  50; W =  76; sc = 0.0625f;  break;
            default: fp = f3; H =  25; W =  38; sc = 0.03125f; break;
        }
        const int b = bidx[roi];
        sBase = fp + (size_t)b * NCH * H * W;
        sH = H; sW = W; sHW = H * W;
        sX0 = x0 * sc - 0.5f;
        sY0 = y0 * sc - 0.5f;
        sBw = (x1 - x0) * sc * (1.0f / NOUT);
        sBh = (y1 - y0) * sc * (1.0f / NOUT);
    }
    __syncthreads();

    // Axis weights: threads [0,14) handle x, [14,28) handle y.
    if (tid < 2 * NS) {
        const int  s   = (tid < NS) ? tid : tid - NS;
        const bool isY = (tid >= NS);
        const float off = (s + 0.5f) * 0.5f;   // s//2 + (s%2 + 0.5)/2
        const float c   = isY ? (sY0 + sBh * off) : (sX0 + sBw * off);
        const int   n   = isY ? sH : sW;
        const float fn  = (float)n;
        const float valid = (c >= -1.0f && c <= fn) ? 1.0f : 0.0f;
        const float cc    = fmaxf(c, 0.0f);
        const float lo_f  = floorf(cc);
        const bool  cap   = (lo_f >= fn - 1.0f);
        const int   lo    = cap ? (n - 1) : (int)lo_f;
        const int   hi    = cap ? (n - 1) : (lo + 1);
        const float l     = cap ? 0.0f : (cc - lo_f);
        const float wl    = (1.0f - l) * valid;
        const float wh    = l * valid;
        if (isY) {
            sYloW[s] = lo * sW; sYhiW[s] = hi * sW;
            sWyl[s] = wl;       sWyh[s] = wh;
        } else {
            sXlo[s] = lo;       sXhi[s] = hi;
            sWxl[s] = wl;       sWxh[s] = wh;
        }
    }
    __syncthreads();

    // Thread mapping: group = tid/49 (0..4 valid), bin = tid%49.
    // 245/256 threads active (95.7% lane efficiency). Each thread keeps its
    // bin FIXED with tap metadata in registers, looping channels c = group,
    // group+5, ... over this block's 64-channel slice.
    const int group = tid / NBIN;          // 0..5
    const int bin   = tid - group * NBIN;  // 0..48
    const bool vld  = (group < NGRP);
    const int ph    = bin / 7;
    const int pw    = bin - ph * 7;

    // Separable 4x4 tap structure: out = sum_a wy[a] * sum_b wx[b] * f[row_a + col_b]
    int   rowOff[4], colOff[4];
    float wy[4], wx[4];
    {
        const int iy0 = ph * 2, iy1 = iy0 + 1;
        rowOff[0] = sYloW[iy0]; wy[0] = sWyl[iy0] * 0.25f;
        rowOff[1] = sYhiW[iy0]; wy[1] = sWyh[iy0] * 0.25f;
        rowOff[2] = sYloW[iy1]; wy[2] = sWyl[iy1] * 0.25f;
        rowOff[3] = sYhiW[iy1]; wy[3] = sWyh[iy1] * 0.25f;
        const int ix0 = pw * 2, ix1 = ix0 + 1;
        colOff[0] = sXlo[ix0];  wx[0] = sWxl[ix0];
        colOff[1] = sXhi[ix0];  wx[1] = sWxh[ix0];
        colOff[2] = sXlo[ix1];  wx[2] = sWxl[ix1];
        colOff[3] = sXhi[ix1];  wx[3] = sWxh[ix1];
    }

    if (vld) {
        const float* __restrict__ base = sBase;
        const int HW = sHW;
        const int cb = blockIdx.y * CPB;   // this block's channel base
        float* __restrict__ outRoi = out + (size_t)roi * ELEMS;

        #pragma unroll 4
        for (int c = group; c < CPB; c += NGRP) {
            const float* __restrict__ fc = base + (cb + c) * HW;
            float acc = 0.0f;
            #pragma unroll
            for (int a = 0; a < 4; a++) {
                const float* __restrict__ fr = fc + rowOff[a];
                float t = 0.0f;
                #pragma unroll
                for (int b = 0; b < 4; b++) {
                    t += wx[b] * __ldg(fr + colOff[b]);
                }
                acc += wy[a] * t;
            }
            outRoi[(cb + c) * NBIN + bin] = acc;
        }
    }
}

extern "C" void kernel_launch(void* const* d_in, const int* in_sizes, int n_in,
                              void* d_out, int out_size) {
    const float* f0    = (const float*)d_in[0];
    const float* f1    = (const float*)d_in[1];
    const float* f2    = (const float*)d_in[2];
    const float* f3    = (const float*)d_in[3];
    const float* boxes = (const float*)d_in[4];
    const int*   bidx  = (const int*)d_in[5];
    float*       out   = (float*)d_out;

    const int M = in_sizes[4] / 4;   // boxes is (M, 4)
    dim3 grid(M, CH_SPLIT);
    roi_pooler_kernel<<<grid, 256>>>(f0, f1, f2, f3, boxes, bidx, out);
}